// round 2
// baseline (speedup 1.0000x reference)
#include <cuda_runtime.h>

#define H 128
#define N_X 250000
#define N_SRC 50000
#define N_Y 50000
#define N_INT 500000
#define E_NODE 1000000
#define E_DOM 500000
#define BN_EPS 1e-5f

// ------------------------- scratch (device globals) -------------------------
__device__ float g_xsum[N_SRC * H];         // raw segment sum of x      (25.6 MB)
__device__ float g_xsum_lin[N_SRC * H];     // g_xsum @ W_xsum^T         (25.6 MB)
__device__ float g_ylin[N_Y * H];           // y @ W_y^T                 (25.6 MB)
__device__ float g_xlin[N_X * H];           // x @ W_xint^T              (128 MB)
__device__ float g_msg[E_DOM * H];          // messages                  (256 MB)
__device__ float g_stats[2 * H];            // col sums / sumsq
__device__ float g_mv[2 * H];               // scale / shift

// ------------------------- helpers -------------------------
__device__ __forceinline__ float plo(unsigned long long v) {
    return __uint_as_float((unsigned)(v & 0xffffffffull));
}
__device__ __forceinline__ float phi(unsigned long long v) {
    return __uint_as_float((unsigned)(v >> 32));
}

// ------------------------- kernel 1: x -> domain segment sum -------------------------
// domain_indicator is SORTED: run-length accumulate in registers, flush with atomics.
#define RX 125
__global__ void xsum_scatter(const float* __restrict__ x,
                             const int* __restrict__ dom,
                             float* __restrict__ xsum) {
    int c = threadIdx.x;               // column 0..127
    int r0 = blockIdx.x * RX;
    int cur = dom[r0];
    float acc = 0.f;
    for (int r = r0; r < r0 + RX; r++) {
        int d = dom[r];
        if (d != cur) {
            atomicAdd(&xsum[(size_t)cur * H + c], acc);
            acc = 0.f;
            cur = d;
        }
        acc += x[(size_t)r * H + c];
    }
    atomicAdd(&xsum[(size_t)cur * H + c], acc);
}

// ------------------------- kernel 2: GEMM out = in @ W^T -------------------------
// 128 threads/block, 32 rows/block. W packed as k-pairs in shared:
// wtp[k2*264 + j*2 + (k&1)]. Each thread: 8 rows x 4 cols, fma.rn.f32x2.
#define GR 32
#define WTP_STRIDE 264
#define SMEM_GEMM ((64 * WTP_STRIDE + GR * H) * 4)

__global__ void gemm128(const float* __restrict__ in, const float* __restrict__ W,
                        float* __restrict__ out, int nrows) {
    extern __shared__ float sm[];
    float* wtp = sm;                    // 64 * 264 floats
    float* xs  = sm + 64 * WTP_STRIDE;  // 32 * 128 floats
    int tid = threadIdx.x;

    // fill packed W: thread tid owns row j=tid of W; k runs over i.
    #pragma unroll 4
    for (int i = 0; i < H; i++) {
        wtp[(i >> 1) * WTP_STRIDE + tid * 2 + (i & 1)] = W[tid * H + i];
    }
    int rb = blockIdx.x * GR;
    #pragma unroll 4
    for (int i = 0; i < GR; i++) {
        int r = rb + i;
        xs[i * H + tid] = (r < nrows) ? in[(size_t)r * H + tid] : 0.f;
    }
    __syncthreads();

    int cg = tid & 31;   // col group: cols cg*4 .. cg*4+3
    int rg = tid >> 5;   // row group: rows rg*8 .. rg*8+7
    unsigned long long acc[8][4];
    #pragma unroll
    for (int r = 0; r < 8; r++)
        #pragma unroll
        for (int j = 0; j < 4; j++) acc[r][j] = 0ull;

    const float* xr = xs + rg * 8 * H;
    #pragma unroll 4
    for (int k2 = 0; k2 < 64; k2++) {
        const float* wp = wtp + k2 * WTP_STRIDE + cg * 8;
        ulonglong2 wa = *reinterpret_cast<const ulonglong2*>(wp);
        ulonglong2 wb = *reinterpret_cast<const ulonglong2*>(wp + 4);
        unsigned long long w0 = wa.x, w1 = wa.y, w2 = wb.x, w3 = wb.y;
        #pragma unroll
        for (int r = 0; r < 8; r++) {
            unsigned long long xp =
                *reinterpret_cast<const unsigned long long*>(xr + r * H + k2 * 2);
            asm("fma.rn.f32x2 %0, %1, %2, %0;" : "+l"(acc[r][0]) : "l"(xp), "l"(w0));
            asm("fma.rn.f32x2 %0, %1, %2, %0;" : "+l"(acc[r][1]) : "l"(xp), "l"(w1));
            asm("fma.rn.f32x2 %0, %1, %2, %0;" : "+l"(acc[r][2]) : "l"(xp), "l"(w2));
            asm("fma.rn.f32x2 %0, %1, %2, %0;" : "+l"(acc[r][3]) : "l"(xp), "l"(w3));
        }
    }

    #pragma unroll
    for (int r = 0; r < 8; r++) {
        int row = rb + rg * 8 + r;
        if (row < nrows) {
            float4 o;
            o.x = plo(acc[r][0]) + phi(acc[r][0]);
            o.y = plo(acc[r][1]) + phi(acc[r][1]);
            o.z = plo(acc[r][2]) + phi(acc[r][2]);
            o.w = plo(acc[r][3]) + phi(acc[r][3]);
            *reinterpret_cast<float4*>(&out[(size_t)row * H + cg * 4]) = o;
        }
    }
}

// ------------------------- kernel 3: fused message + BN stats -------------------------
// msg[e] = xsum_lin[dm0[e]] + sum_{j: ii[j]==e} xlin[nm0[j]] + ylin[dm1[e]]
// intersect_indicator (ii) is sorted: binary search per row -> NO atomics for x_int.
// Per-column BN sums/sumsq accumulated over 64 rows/block in registers.
#define MROWS 64
__global__ void msg_kernel(const float* __restrict__ xlin,
                           const float* __restrict__ xsum_lin,
                           const float* __restrict__ ylin,
                           const int* __restrict__ nm0,
                           const int* __restrict__ ii,
                           const int* __restrict__ dm0,
                           const int* __restrict__ dm1,
                           float* __restrict__ msg,
                           float* __restrict__ stats) {
    __shared__ int s_lo[MROWS + 1];
    int c = threadIdx.x;
    int e_base = blockIdx.x * MROWS;

    if (threadIdx.x <= MROWS) {
        int target = e_base + threadIdx.x;
        int lo = 0, hi = E_NODE;
        while (lo < hi) {
            int mid = (lo + hi) >> 1;
            if (ii[mid] < target) lo = mid + 1; else hi = mid;
        }
        s_lo[threadIdx.x] = lo;
    }
    __syncthreads();

    float csum = 0.f, csq = 0.f;
    for (int r = 0; r < MROWS; r++) {
        int e = e_base + r;
        if (e >= E_DOM) break;
        float acc = 0.f;
        int jend = s_lo[r + 1];
        for (int j = s_lo[r]; j < jend; j++) {
            acc += xlin[(size_t)nm0[j] * H + c];
        }
        acc += xsum_lin[(size_t)dm0[e] * H + c];
        acc += ylin[(size_t)dm1[e] * H + c];
        msg[(size_t)e * H + c] = acc;
        csum += acc;
        csq += acc * acc;
    }
    atomicAdd(&stats[c], csum);
    atomicAdd(&stats[H + c], csq);
}

// ------------------------- kernel 4: BN finalize -------------------------
__global__ void bn_finalize(const float* __restrict__ stats,
                            const float* __restrict__ bn_w,
                            const float* __restrict__ bn_b,
                            float* __restrict__ mv) {
    int c = threadIdx.x;
    float inv_n = 1.f / (float)E_DOM;
    float mean = stats[c] * inv_n;
    float var = stats[H + c] * inv_n - mean * mean;
    float s = bn_w[c] * rsqrtf(var + BN_EPS);
    mv[c] = s;
    mv[H + c] = bn_b[c] - mean * s;
}

// ------------------------- kernel 5: normalize + ReLU + scatter to targets -------------------------
#define ER 125
__global__ void out_scatter(const float* __restrict__ msg,
                            const int* __restrict__ dm1,
                            const float* __restrict__ mv,
                            float* __restrict__ out) {
    int c = threadIdx.x;
    int e0 = blockIdx.x * ER;
    float scale = mv[c];
    float shift = mv[H + c];
    for (int e = e0; e < e0 + ER; e++) {
        float v = msg[(size_t)e * H + c] * scale + shift;
        v = fmaxf(v, 0.f);
        atomicAdd(&out[(size_t)dm1[e] * H + c], v);
    }
}

// ------------------------- launch -------------------------
extern "C" void kernel_launch(void* const* d_in, const int* in_sizes, int n_in,
                              void* d_out, int out_size) {
    const float* x      = (const float*)d_in[0];
    const float* y      = (const float*)d_in[1];
    const int*   dom    = (const int*)d_in[2];
    const int*   nm     = (const int*)d_in[3];
    const int*   ii     = (const int*)d_in[4];
    const int*   dm     = (const int*)d_in[5];
    const float* W_xsum = (const float*)d_in[6];
    const float* W_xint = (const float*)d_in[7];
    const float* W_y    = (const float*)d_in[8];
    const float* bn_w   = (const float*)d_in[9];
    const float* bn_b   = (const float*)d_in[10];
    float* out = (float*)d_out;

    const int* nm0 = nm;            // node_map_edge_index[0]
    const int* dm0 = dm;            // domain_map_edge_index[0]
    const int* dm1 = dm + E_DOM;    // domain_map_edge_index[1]

    void *p_xsum, *p_xsum_lin, *p_ylin, *p_xlin, *p_msg, *p_stats, *p_mv;
    cudaGetSymbolAddress(&p_xsum, g_xsum);
    cudaGetSymbolAddress(&p_xsum_lin, g_xsum_lin);
    cudaGetSymbolAddress(&p_ylin, g_ylin);
    cudaGetSymbolAddress(&p_xlin, g_xlin);
    cudaGetSymbolAddress(&p_msg, g_msg);
    cudaGetSymbolAddress(&p_stats, g_stats);
    cudaGetSymbolAddress(&p_mv, g_mv);

    cudaFuncSetAttribute(gemm128, cudaFuncAttributeMaxDynamicSharedMemorySize, SMEM_GEMM);

    cudaMemsetAsync(p_xsum, 0, sizeof(float) * (size_t)N_SRC * H, 0);
    cudaMemsetAsync(p_stats, 0, sizeof(float) * 2 * H, 0);
    cudaMemsetAsync(d_out, 0, sizeof(float) * (size_t)out_size, 0);

    xsum_scatter<<<N_X / RX, 128>>>(x, dom, (float*)p_xsum);

    gemm128<<<(N_X + GR - 1) / GR, 128, SMEM_GEMM>>>(x, W_xint, (float*)p_xlin, N_X);
    gemm128<<<(N_SRC + GR - 1) / GR, 128, SMEM_GEMM>>>((const float*)p_xsum, W_xsum,
                                                       (float*)p_xsum_lin, N_SRC);
    gemm128<<<(N_Y + GR - 1) / GR, 128, SMEM_GEMM>>>(y, W_y, (float*)p_ylin, N_Y);

    msg_kernel<<<(E_DOM + MROWS - 1) / MROWS, 128>>>((const float*)p_xlin,
                                                     (const float*)p_xsum_lin,
                                                     (const float*)p_ylin,
                                                     nm0, ii, dm0, dm1,
                                                     (float*)p_msg, (float*)p_stats);

    bn_finalize<<<1, 128>>>((const float*)p_stats, bn_w, bn_b, (float*)p_mv);

    out_scatter<<<E_DOM / ER, 128>>>((const float*)p_msg, dm1, (const float*)p_mv, out);
}

// round 4
// speedup vs baseline: 1.7711x; 1.7711x over previous
#include <cuda_runtime.h>

#define H 128
#define N_X 250000
#define N_SRC 50000
#define N_Y 50000
#define N_INT 500000
#define E_NODE 1000000
#define E_DOM 500000
#define BN_EPS 1e-5f

// ------------------------- scratch (device globals) -------------------------
__device__ float g_xsum[N_SRC * H];
__device__ float g_xsum_lin[N_SRC * H];
__device__ float g_ylin[N_Y * H];
__device__ float g_xlin[N_X * H];
__device__ float g_msg[E_DOM * H];
__device__ float g_stats[2 * H];
__device__ float g_mv[2 * H];

// ------------------------- kernel 1: x -> domain segment sum (R1-proven) -------------------------
#define RX 125
__global__ void xsum_scatter(const float* __restrict__ x,
                             const int* __restrict__ dom,
                             float* __restrict__ xsum) {
    int c = threadIdx.x;               // column 0..127
    int r0 = blockIdx.x * RX;
    int cur = dom[r0];
    float acc = 0.f;
    for (int r = r0; r < r0 + RX; r++) {
        int d = dom[r];
        if (d != cur) {
            atomicAdd(&xsum[(size_t)cur * H + c], acc);
            acc = 0.f;
            cur = d;
        }
        acc += x[(size_t)r * H + c];
    }
    atomicAdd(&xsum[(size_t)cur * H + c], acc);
}

// ------------------------- kernel 2: GEMM out = in @ W^T -------------------------
// 256 threads, 128 rows x 128 cols per block. W transposed into smem (coalesced LDG),
// full 128-k x tile staged via float4 LDG->STS. FFMA2 over column pairs (no final hadd).
#define GR 128
#define XPAD 132
#define WPAD 132
#define SMEM_GEMM ((H * WPAD + GR * XPAD) * 4)

__global__ void __launch_bounds__(256, 1)
gemm128(const float* __restrict__ in, const float* __restrict__ W,
        float* __restrict__ out, int nrows) {
    extern __shared__ float sm[];
    float* wt = sm;                 // [k][c] transposed W, stride WPAD
    float* xs = sm + H * WPAD;      // [row][k], stride XPAD
    int tid = threadIdx.x;
    int lane = tid & 31;
    int wrp = tid >> 5;
    int cgrp = tid & 15;            // cols cgrp*8 .. +7
    int rgrp = tid >> 4;            // rows rgrp*8 .. +7
    int rb = blockIdx.x * GR;

    // transpose W into smem: coalesced LDG along k
    #pragma unroll
    for (int i = 0; i < 16; i++) {
        int c = wrp * 16 + i;
        const float* Wr = W + (size_t)c * H;
        #pragma unroll
        for (int j = 0; j < 4; j++) {
            int k = j * 32 + lane;
            wt[k * WPAD + c] = Wr[k];
        }
    }

    // stage x tile: 128 rows x 128 k, float4 chunks, coalesced
    #pragma unroll
    for (int i = 0; i < 16; i++) {
        int cid = i * 256 + tid;        // 4096 chunks: 128 rows x 32 chunks
        int row = cid >> 5;
        int q = (cid & 31) * 4;
        int grow = rb + row;
        float4 v = make_float4(0.f, 0.f, 0.f, 0.f);
        if (grow < nrows)
            v = *reinterpret_cast<const float4*>(&in[(size_t)grow * H + q]);
        *reinterpret_cast<float4*>(&xs[row * XPAD + q]) = v;
    }
    __syncthreads();

    unsigned long long acc[8][4];
    #pragma unroll
    for (int r = 0; r < 8; r++)
        #pragma unroll
        for (int j = 0; j < 4; j++) acc[r][j] = 0ull;

    const float* xr = xs + rgrp * 8 * XPAD;
    #pragma unroll 4
    for (int k = 0; k < H; k++) {
        const float* wb = wt + k * WPAD + cgrp * 8;
        ulonglong2 wa = *reinterpret_cast<const ulonglong2*>(wb);
        ulonglong2 wc = *reinterpret_cast<const ulonglong2*>(wb + 4);
        #pragma unroll
        for (int r = 0; r < 8; r++) {
            unsigned xu = __float_as_uint(xr[r * XPAD + k]);
            unsigned long long xd;
            asm("mov.b64 %0, {%1, %1};" : "=l"(xd) : "r"(xu));
            asm("fma.rn.f32x2 %0, %1, %2, %0;" : "+l"(acc[r][0]) : "l"(xd), "l"(wa.x));
            asm("fma.rn.f32x2 %0, %1, %2, %0;" : "+l"(acc[r][1]) : "l"(xd), "l"(wa.y));
            asm("fma.rn.f32x2 %0, %1, %2, %0;" : "+l"(acc[r][2]) : "l"(xd), "l"(wc.x));
            asm("fma.rn.f32x2 %0, %1, %2, %0;" : "+l"(acc[r][3]) : "l"(xd), "l"(wc.y));
        }
    }

    #pragma unroll
    for (int r = 0; r < 8; r++) {
        int row = rb + rgrp * 8 + r;
        if (row < nrows) {
            float* op = &out[(size_t)row * H + cgrp * 8];
            *reinterpret_cast<ulonglong2*>(op) = make_ulonglong2(acc[r][0], acc[r][1]);
            *reinterpret_cast<ulonglong2*>(op + 4) = make_ulonglong2(acc[r][2], acc[r][3]);
        }
    }
}

// ------------------------- kernel 3: fused message + BN stats (proven) -------------------------
#define MROWS 64
__global__ void msg_kernel(const float* __restrict__ xlin,
                           const float* __restrict__ xsum_lin,
                           const float* __restrict__ ylin,
                           const int* __restrict__ nm0,
                           const int* __restrict__ ii,
                           const int* __restrict__ dm0,
                           const int* __restrict__ dm1,
                           float* __restrict__ msg,
                           float* __restrict__ stats) {
    __shared__ int s_lo[MROWS + 1];
    int c = threadIdx.x;
    int e_base = blockIdx.x * MROWS;

    if (threadIdx.x <= MROWS) {
        int target = e_base + threadIdx.x;
        int lo = 0, hi = E_NODE;
        while (lo < hi) {
            int mid = (lo + hi) >> 1;
            if (ii[mid] < target) lo = mid + 1; else hi = mid;
        }
        s_lo[threadIdx.x] = lo;
    }
    __syncthreads();

    float csum = 0.f, csq = 0.f;
    for (int r = 0; r < MROWS; r++) {
        int e = e_base + r;
        if (e >= E_DOM) break;
        float acc = 0.f;
        int jend = s_lo[r + 1];
        for (int j = s_lo[r]; j < jend; j++) {
            acc += xlin[(size_t)nm0[j] * H + c];
        }
        acc += xsum_lin[(size_t)dm0[e] * H + c];
        acc += ylin[(size_t)dm1[e] * H + c];
        msg[(size_t)e * H + c] = acc;
        csum += acc;
        csq += acc * acc;
    }
    atomicAdd(&stats[c], csum);
    atomicAdd(&stats[H + c], csq);
}

// ------------------------- kernel 4: BN finalize (proven) -------------------------
__global__ void bn_finalize(const float* __restrict__ stats,
                            const float* __restrict__ bn_w,
                            const float* __restrict__ bn_b,
                            float* __restrict__ mv) {
    int c = threadIdx.x;
    float inv_n = 1.f / (float)E_DOM;
    float mean = stats[c] * inv_n;
    float var = stats[H + c] * inv_n - mean * mean;
    float s = bn_w[c] * rsqrtf(var + BN_EPS);
    mv[c] = s;
    mv[H + c] = bn_b[c] - mean * s;
}

// ------------------------- kernel 5: normalize + ReLU + scatter (R1-proven) -------------------------
#define ER 125
__global__ void out_scatter(const float* __restrict__ msg,
                            const int* __restrict__ dm1,
                            const float* __restrict__ mv,
                            float* __restrict__ out) {
    int c = threadIdx.x;
    int e0 = blockIdx.x * ER;
    float scale = mv[c];
    float shift = mv[H + c];
    for (int e = e0; e < e0 + ER; e++) {
        float v = msg[(size_t)e * H + c] * scale + shift;
        v = fmaxf(v, 0.f);
        atomicAdd(&out[(size_t)dm1[e] * H + c], v);
    }
}

// ------------------------- launch -------------------------
extern "C" void kernel_launch(void* const* d_in, const int* in_sizes, int n_in,
                              void* d_out, int out_size) {
    const float* x      = (const float*)d_in[0];
    const float* y      = (const float*)d_in[1];
    const int*   dom    = (const int*)d_in[2];
    const int*   nm     = (const int*)d_in[3];
    const int*   ii     = (const int*)d_in[4];
    const int*   dm     = (const int*)d_in[5];
    const float* W_xsum = (const float*)d_in[6];
    const float* W_xint = (const float*)d_in[7];
    const float* W_y    = (const float*)d_in[8];
    const float* bn_w   = (const float*)d_in[9];
    const float* bn_b   = (const float*)d_in[10];
    float* out = (float*)d_out;

    const int* nm0 = nm;
    const int* dm0 = dm;
    const int* dm1 = dm + E_DOM;

    void *p_xsum, *p_xsum_lin, *p_ylin, *p_xlin, *p_msg, *p_stats, *p_mv;
    cudaGetSymbolAddress(&p_xsum, g_xsum);
    cudaGetSymbolAddress(&p_xsum_lin, g_xsum_lin);
    cudaGetSymbolAddress(&p_ylin, g_ylin);
    cudaGetSymbolAddress(&p_xlin, g_xlin);
    cudaGetSymbolAddress(&p_msg, g_msg);
    cudaGetSymbolAddress(&p_stats, g_stats);
    cudaGetSymbolAddress(&p_mv, g_mv);

    cudaFuncSetAttribute(gemm128, cudaFuncAttributeMaxDynamicSharedMemorySize, SMEM_GEMM);

    cudaMemsetAsync(p_xsum, 0, sizeof(float) * (size_t)N_SRC * H, 0);
    cudaMemsetAsync(p_stats, 0, sizeof(float) * 2 * H, 0);
    cudaMemsetAsync(d_out, 0, sizeof(float) * (size_t)out_size, 0);

    xsum_scatter<<<N_X / RX, 128>>>(x, dom, (float*)p_xsum);

    gemm128<<<(N_X + GR - 1) / GR, 256, SMEM_GEMM>>>(x, W_xint, (float*)p_xlin, N_X);
    gemm128<<<(N_SRC + GR - 1) / GR, 256, SMEM_GEMM>>>((const float*)p_xsum, W_xsum,
                                                       (float*)p_xsum_lin, N_SRC);
    gemm128<<<(N_Y + GR - 1) / GR, 256, SMEM_GEMM>>>(y, W_y, (float*)p_ylin, N_Y);

    msg_kernel<<<(E_DOM + MROWS - 1) / MROWS, 128>>>((const float*)p_xlin,
                                                     (const float*)p_xsum_lin,
                                                     (const float*)p_ylin,
                                                     nm0, ii, dm0, dm1,
                                                     (float*)p_msg, (float*)p_stats);

    bn_finalize<<<1, 128>>>((const float*)p_stats, bn_w, bn_b, (float*)p_mv);

    out_scatter<<<E_DOM / ER, 128>>>((const float*)p_msg, dm1, (const float*)p_mv, out);
}